// round 1
// baseline (speedup 1.0000x reference)
#include <cuda_runtime.h>
#include <cstdint>

#define Bdim 256
#define Ddim 128
#define Cdim 8000
#define CPAD 8064
#define SCALE_F 64.0f
#define MARGIN_F 0.5f
#define EPS_F 1e-12f

// ---------------- device scratch (no allocations allowed) ----------------
__device__ float g_nw[Ddim * CPAD];   // normalized w, [d][c], padded cols zeroed
__device__ float g_neT[Ddim * Bdim];  // normalized embds, transposed [d][b]
__device__ float g_grT[Ddim * Bdim];  // gathered label columns, transposed [d][b]
__device__ float g_s[Bdim];           // s[b] = ne[b] . gr[b]
__device__ float g_cos[Bdim * CPAD];  // cos_t scratch for softmax

// ---------------- f32x2 helpers ----------------
__device__ __forceinline__ unsigned long long pack2(float x, float y) {
    unsigned long long r;
    asm("mov.b64 %0, {%1, %2};" : "=l"(r) : "f"(x), "f"(y));
    return r;
}
__device__ __forceinline__ void ffma2(unsigned long long& d,
                                      unsigned long long a,
                                      unsigned long long b) {
    asm("fma.rn.f32x2 %0, %1, %2, %0;" : "+l"(d) : "l"(a), "l"(b));
}
__device__ __forceinline__ float2 unpack2(unsigned long long v) {
    float2 f;
    asm("mov.b64 {%0, %1}, %2;" : "=f"(f.x), "=f"(f.y) : "l"(v));
    return f;
}

// ---------------- K1: normalize columns of w ----------------
__global__ void k_norm_w(const float* __restrict__ w) {
    int c = blockIdx.x * 256 + threadIdx.x;
    if (c >= CPAD) return;
    if (c < Cdim) {
        float ss = 0.f;
#pragma unroll 8
        for (int d = 0; d < Ddim; d++) {
            float v = w[d * Cdim + c];
            ss = fmaf(v, v, ss);
        }
        float r = rsqrtf(fmaxf(ss, EPS_F));
#pragma unroll 8
        for (int d = 0; d < Ddim; d++) {
            g_nw[d * CPAD + c] = w[d * Cdim + c] * r;
        }
    } else {
#pragma unroll 8
        for (int d = 0; d < Ddim; d++) g_nw[d * CPAD + c] = 0.f;
    }
}

// ---------------- K2: normalize embds, gather gr, compute s ----------------
__global__ void k_prep(const float* __restrict__ embds,
                       const int* __restrict__ labels) {
    int b = blockIdx.x;
    int d = threadIdx.x;  // 128 threads
    __shared__ float redA[4];
    __shared__ float redB[4];

    float e = embds[b * Ddim + d];
    float v = e * e;
#pragma unroll
    for (int o = 16; o > 0; o >>= 1) v += __shfl_xor_sync(0xffffffffu, v, o);
    if ((d & 31) == 0) redA[d >> 5] = v;
    __syncthreads();
    float ss = redA[0] + redA[1] + redA[2] + redA[3];
    float r = rsqrtf(fmaxf(ss, EPS_F));
    float ne = e * r;

    int lb = labels[b];
    float gr = g_nw[d * CPAD + lb];

    g_neT[d * Bdim + b] = ne;
    g_grT[d * Bdim + b] = gr;

    float sv = ne * gr;
#pragma unroll
    for (int o = 16; o > 0; o >>= 1) sv += __shfl_xor_sync(0xffffffffu, sv, o);
    if ((d & 31) == 0) redB[d >> 5] = sv;
    __syncthreads();
    if (d == 0) g_s[b] = redB[0] + redB[1] + redB[2] + redB[3];
}

// ---------------- K3: fused dual GEMM + penalty epilogue ----------------
#define BT 64
#define CT 128
// smem: sNw[128][128] (64KB) + sNe[128][64] (32KB) + sGr[128][64] (32KB) = 128KB

__global__ __launch_bounds__(256, 1) void k_main(float* __restrict__ out_pen,
                                                 const int* __restrict__ labels) {
    extern __shared__ float smem[];
    float* sNw = smem;                 // [k][c] CT floats per row
    float* sNe = smem + Ddim * CT;     // [k][b] BT floats per row
    float* sGr = sNe + Ddim * BT;

    const int tid = threadIdx.x;
    const int cBase = blockIdx.x * CT;
    const int bBase = blockIdx.y * BT;

    // ---- load tiles (full K resident) ----
    float4* sNw4 = (float4*)sNw;
#pragma unroll
    for (int i = 0; i < 16; i++) {
        int f = tid + i * 256;            // 4096 float4 total
        int k = f >> 5;                   // CT/4 = 32 float4 per row
        int co = (f & 31) << 2;
        sNw4[f] = *(const float4*)&g_nw[k * CPAD + cBase + co];
    }
    float4* sNe4 = (float4*)sNe;
    float4* sGr4 = (float4*)sGr;
#pragma unroll
    for (int i = 0; i < 8; i++) {
        int f = tid + i * 256;            // 2048 float4 total
        int k = f >> 4;                   // BT/4 = 16 float4 per row
        int bo = (f & 15) << 2;
        sNe4[f] = *(const float4*)&g_neT[k * Bdim + bBase + bo];
        sGr4[f] = *(const float4*)&g_grT[k * Bdim + bBase + bo];
    }
    __syncthreads();

    const int tx = tid & 15;   // c group: c = tx*4 (+64)
    const int ty = tid >> 4;   // b group: b = ty*4

    unsigned long long accC[4][4];
    unsigned long long accG[4][4];
#pragma unroll
    for (int i = 0; i < 4; i++)
#pragma unroll
        for (int j = 0; j < 4; j++) { accC[i][j] = 0ull; accG[i][j] = 0ull; }

#pragma unroll 4
    for (int k = 0; k < Ddim; k++) {
        float4 neV = sNe4[k * (BT / 4) + ty];
        float4 grV = sGr4[k * (BT / 4) + ty];
        const ulonglong2* nwr = (const ulonglong2*)&sNw[k * CT];
        ulonglong2 nwA = nwr[tx];        // c = tx*4 .. tx*4+3
        ulonglong2 nwB = nwr[16 + tx];   // c = 64 + tx*4 ..
        unsigned long long nwp[4] = {nwA.x, nwA.y, nwB.x, nwB.y};
        unsigned long long nep[4] = {pack2(neV.x, neV.x), pack2(neV.y, neV.y),
                                     pack2(neV.z, neV.z), pack2(neV.w, neV.w)};
        unsigned long long grp[4] = {pack2(grV.x, grV.x), pack2(grV.y, grV.y),
                                     pack2(grV.z, grV.z), pack2(grV.w, grV.w)};
#pragma unroll
        for (int i = 0; i < 4; i++) {
#pragma unroll
            for (int j = 0; j < 4; j++) {
                ffma2(accC[i][j], nep[i], nwp[j]);
                ffma2(accG[i][j], grp[i], nwp[j]);
            }
        }
    }

    // ---- epilogue: penalties + cos scratch ----
#pragma unroll
    for (int i = 0; i < 4; i++) {
        int b = bBase + ty * 4 + i;
        float sb = g_s[b];
        int lb = labels[b];
#pragma unroll
        for (int h = 0; h < 2; h++) {
            int c0 = cBase + h * 64 + tx * 4;
            float2 cA = unpack2(accC[i][h * 2 + 0]);
            float2 cB = unpack2(accC[i][h * 2 + 1]);
            float2 gA = unpack2(accG[i][h * 2 + 0]);
            float2 gB = unpack2(accG[i][h * 2 + 1]);
            float cosv[4] = {cA.x, cA.y, cB.x, cB.y};
            float Gv[4]   = {gA.x, gA.y, gB.x, gB.y};
            float pen[4];
#pragma unroll
            for (int j = 0; j < 4; j++) {
                float denom = fmaxf(2.f - 2.f * Gv[j], EPS_F);
                float win = (sb - cosv[j]) * rsqrtf(denom);
                if (c0 + j == lb) win = 0.f;  // dw==0 exactly in reference
                pen[j] = MARGIN_F - fminf(MARGIN_F, win);
            }
            *(float4*)&g_cos[b * CPAD + c0] =
                make_float4(cosv[0], cosv[1], cosv[2], cosv[3]);
            if (c0 < Cdim) {  // c0 % 4 == 0 and Cdim % 4 == 0 -> whole vec valid
                *(float4*)&out_pen[(size_t)b * Cdim + c0] =
                    make_float4(pen[0], pen[1], pen[2], pen[3]);
            }
        }
    }
}

// ---------------- K4: row softmax of SCALE * cos ----------------
__global__ __launch_bounds__(256) void k_softmax(float* __restrict__ out) {
    __shared__ float row[Cdim];   // 32KB
    __shared__ float redA[8];
    __shared__ float redB[8];
    int b = blockIdx.x;
    int tid = threadIdx.x;
    int lane = tid & 31, wid = tid >> 5;
    const float* src = &g_cos[b * CPAD];

    float m = -3.402823e38f;
    for (int c = tid; c < Cdim; c += 256) {
        float v = src[c];
        row[c] = v;
        m = fmaxf(m, v);
    }
#pragma unroll
    for (int o = 16; o > 0; o >>= 1) m = fmaxf(m, __shfl_xor_sync(0xffffffffu, m, o));
    if (lane == 0) redA[wid] = m;
    __syncthreads();
    float mAll = redA[0];
#pragma unroll
    for (int i = 1; i < 8; i++) mAll = fmaxf(mAll, redA[i]);
    float mScaled = SCALE_F * mAll;

    float s = 0.f;
    for (int c = tid; c < Cdim; c += 256) {
        float e = expf(SCALE_F * row[c] - mScaled);
        row[c] = e;
        s += e;
    }
#pragma unroll
    for (int o = 16; o > 0; o >>= 1) s += __shfl_xor_sync(0xffffffffu, s, o);
    if (lane == 0) redB[wid] = s;
    __syncthreads();
    float sAll = 0.f;
#pragma unroll
    for (int i = 0; i < 8; i++) sAll += redB[i];
    float inv = 1.f / sAll;

    for (int c = tid; c < Cdim; c += 256) {
        out[(size_t)b * Cdim + c] = row[c] * inv;
    }
}

// ---------------- launch ----------------
extern "C" void kernel_launch(void* const* d_in, const int* in_sizes, int n_in,
                              void* d_out, int out_size) {
    const float* embds = (const float*)d_in[0];   // [256,128]
    const float* w     = (const float*)d_in[1];   // [128,8000]
    const int* labels  = (const int*)d_in[2];     // [256]
    float* out = (float*)d_out;                   // logits[256*8000] then penalties[256*8000]

    static const int kMainSmem = (Ddim * CT + 2 * Ddim * BT) * (int)sizeof(float); // 128KB
    cudaFuncSetAttribute(k_main, cudaFuncAttributeMaxDynamicSharedMemorySize, kMainSmem);

    k_norm_w<<<(CPAD + 255) / 256, 256>>>(w);
    k_prep<<<Bdim, Ddim>>>(embds, labels);

    dim3 g3(CPAD / CT, Bdim / BT);  // (63, 4)
    k_main<<<g3, 256, kMainSmem>>>(out + (size_t)Bdim * Cdim, labels);

    k_softmax<<<Bdim, 256>>>(out);
}

// round 2
// speedup vs baseline: 1.0358x; 1.0358x over previous
#include <cuda_runtime.h>
#include <cstdint>

#define Bdim 256
#define Ddim 128
#define Cdim 8000
#define CPAD 8064
#define SCALE_F 64.0f
#define MARGIN_F 0.5f
#define EPS_F 1e-12f

#define BT 64
#define CT 128
#define KH 64   // K half per staging phase

// ---------------- device scratch (no allocations allowed) ----------------
__device__ float g_nw[Ddim * CPAD];   // normalized w, [d][c], padded cols zeroed
__device__ float g_neT[Ddim * Bdim];  // normalized embds, transposed [d][b]
__device__ float g_grT[Ddim * Bdim];  // gathered label columns, transposed [d][b]
__device__ float g_s[Bdim];           // s[b] = ne[b] . gr[b]
__device__ float g_rowsum[Bdim];      // softmax denominators (atomic-accumulated)

// ---------------- f32x2 helpers ----------------
__device__ __forceinline__ unsigned long long pack2(float x, float y) {
    unsigned long long r;
    asm("mov.b64 %0, {%1, %2};" : "=l"(r) : "f"(x), "f"(y));
    return r;
}
__device__ __forceinline__ void ffma2(unsigned long long& d,
                                      unsigned long long a,
                                      unsigned long long b) {
    asm("fma.rn.f32x2 %0, %1, %2, %0;" : "+l"(d) : "l"(a), "l"(b));
}
__device__ __forceinline__ float2 unpack2(unsigned long long v) {
    float2 f;
    asm("mov.b64 {%0, %1}, %2;" : "=f"(f.x), "=f"(f.y) : "l"(v));
    return f;
}

// ---------------- K1: normalize columns of w ----------------
__global__ void k_norm_w(const float* __restrict__ w) {
    int c = blockIdx.x * 256 + threadIdx.x;
    if (c >= CPAD) return;
    if (c < Cdim) {
        float ss = 0.f;
#pragma unroll 8
        for (int d = 0; d < Ddim; d++) {
            float v = w[d * Cdim + c];
            ss = fmaf(v, v, ss);
        }
        float r = rsqrtf(fmaxf(ss, EPS_F));
#pragma unroll 8
        for (int d = 0; d < Ddim; d++) {
            g_nw[d * CPAD + c] = w[d * Cdim + c] * r;
        }
    } else {
#pragma unroll 8
        for (int d = 0; d < Ddim; d++) g_nw[d * CPAD + c] = 0.f;
    }
}

// ---------------- K2: normalize embds, gather gr, compute s, reset rowsum ----
__global__ void k_prep(const float* __restrict__ embds,
                       const int* __restrict__ labels) {
    int b = blockIdx.x;
    int d = threadIdx.x;  // 128 threads
    __shared__ float redA[4];
    __shared__ float redB[4];

    float e = embds[b * Ddim + d];
    float v = e * e;
#pragma unroll
    for (int o = 16; o > 0; o >>= 1) v += __shfl_xor_sync(0xffffffffu, v, o);
    if ((d & 31) == 0) redA[d >> 5] = v;
    __syncthreads();
    float ss = redA[0] + redA[1] + redA[2] + redA[3];
    float r = rsqrtf(fmaxf(ss, EPS_F));
    float ne = e * r;

    int lb = labels[b];
    float gr = g_nw[d * CPAD + lb];

    g_neT[d * Bdim + b] = ne;
    g_grT[d * Bdim + b] = gr;

    float sv = ne * gr;
#pragma unroll
    for (int o = 16; o > 0; o >>= 1) sv += __shfl_xor_sync(0xffffffffu, sv, o);
    if ((d & 31) == 0) redB[d >> 5] = sv;
    __syncthreads();
    if (d == 0) {
        g_s[b] = redB[0] + redB[1] + redB[2] + redB[3];
        g_rowsum[b] = 0.f;
    }
}

// ---------------- K3: fused dual GEMM + penalty + exp epilogue --------------
// smem per phase: sNw[64][128] 32KB + sNe[64][64] 16KB + sGr[64][64] 16KB = 64KB
// -> 2 CTAs/SM resident.
__global__ __launch_bounds__(256, 2) void k_main(float* __restrict__ out,
                                                 const int* __restrict__ labels) {
    extern __shared__ float smem[];
    float* sNw = smem;                 // [k][c]
    float* sNe = smem + KH * CT;       // [k][b]
    float* sGr = sNe + KH * BT;

    const int tid = threadIdx.x;
    const int cBase = blockIdx.x * CT;
    const int bBase = blockIdx.y * BT;

    const int tx = tid & 15;   // c group
    const int ty = tid >> 4;   // b group

    float4* sNw4 = (float4*)sNw;
    float4* sNe4 = (float4*)sNe;
    float4* sGr4 = (float4*)sGr;

    unsigned long long accC[4][4];
    unsigned long long accG[4][4];
#pragma unroll
    for (int i = 0; i < 4; i++)
#pragma unroll
        for (int j = 0; j < 4; j++) { accC[i][j] = 0ull; accG[i][j] = 0ull; }

#pragma unroll
    for (int ph = 0; ph < 2; ph++) {
        if (ph) __syncthreads();   // consumers of previous phase done
        // ---- stage this K-half ----
#pragma unroll
        for (int i = 0; i < 8; i++) {
            int f = tid + i * 256;            // 2048 float4: 64 k x 32
            int k = f >> 5;
            int co = (f & 31) << 2;
            sNw4[f] = *(const float4*)&g_nw[(ph * KH + k) * CPAD + cBase + co];
        }
#pragma unroll
        for (int i = 0; i < 4; i++) {
            int f = tid + i * 256;            // 1024 float4: 64 k x 16
            int k = f >> 4;
            int bo = (f & 15) << 2;
            sNe4[f] = *(const float4*)&g_neT[(ph * KH + k) * Bdim + bBase + bo];
            sGr4[f] = *(const float4*)&g_grT[(ph * KH + k) * Bdim + bBase + bo];
        }
        __syncthreads();

#pragma unroll 4
        for (int k = 0; k < KH; k++) {
            float4 neV = sNe4[k * (BT / 4) + ty];
            float4 grV = sGr4[k * (BT / 4) + ty];
            const ulonglong2* nwr = (const ulonglong2*)&sNw[k * CT];
            ulonglong2 nwA = nwr[tx];
            ulonglong2 nwB = nwr[16 + tx];
            unsigned long long nwp[4] = {nwA.x, nwA.y, nwB.x, nwB.y};
            unsigned long long nep[4] = {pack2(neV.x, neV.x), pack2(neV.y, neV.y),
                                         pack2(neV.z, neV.z), pack2(neV.w, neV.w)};
            unsigned long long grp[4] = {pack2(grV.x, grV.x), pack2(grV.y, grV.y),
                                         pack2(grV.z, grV.z), pack2(grV.w, grV.w)};
#pragma unroll
            for (int i = 0; i < 4; i++) {
#pragma unroll
                for (int j = 0; j < 4; j++) {
                    ffma2(accC[i][j], nep[i], nwp[j]);
                    ffma2(accG[i][j], grp[i], nwp[j]);
                }
            }
        }
    }

    // ---- epilogue: penalties + exp logits + row-sum atomics ----
    float* out_logit = out;
    float* out_pen = out + (size_t)Bdim * Cdim;

#pragma unroll
    for (int i = 0; i < 4; i++) {
        int b = bBase + ty * 4 + i;
        float sb = g_s[b];
        int lb = labels[b];
        float esum = 0.f;
#pragma unroll
        for (int h = 0; h < 2; h++) {
            int c0 = cBase + h * 64 + tx * 4;
            float2 cA = unpack2(accC[i][h * 2 + 0]);
            float2 cB = unpack2(accC[i][h * 2 + 1]);
            float2 gA = unpack2(accG[i][h * 2 + 0]);
            float2 gB = unpack2(accG[i][h * 2 + 1]);
            float cosv[4] = {cA.x, cA.y, cB.x, cB.y};
            float Gv[4]   = {gA.x, gA.y, gB.x, gB.y};
            if (c0 < Cdim) {  // Cdim % 4 == 0, c0 % 4 == 0 -> whole vec valid
                float pen[4], ev[4];
#pragma unroll
                for (int j = 0; j < 4; j++) {
                    float denom = fmaxf(2.f - 2.f * Gv[j], EPS_F);
                    float win = (sb - cosv[j]) * rsqrtf(denom);
                    if (c0 + j == lb) win = 0.f;  // dw==0 exactly in reference
                    pen[j] = MARGIN_F - fminf(MARGIN_F, win);
                    ev[j] = __expf(SCALE_F * cosv[j] - SCALE_F);
                    esum += ev[j];
                }
                *(float4*)&out_pen[(size_t)b * Cdim + c0] =
                    make_float4(pen[0], pen[1], pen[2], pen[3]);
                *(float4*)&out_logit[(size_t)b * Cdim + c0] =
                    make_float4(ev[0], ev[1], ev[2], ev[3]);
            }
        }
        // reduce esum across the 16 tx lanes (a half-warp: lane = (ty&1)*16+tx)
#pragma unroll
        for (int o = 8; o > 0; o >>= 1)
            esum += __shfl_xor_sync(0xffffffffu, esum, o);
        if (tx == 0) atomicAdd(&g_rowsum[b], esum);
    }
}

// ---------------- K4: scale logits by 1/rowsum ----------------
__global__ __launch_bounds__(256) void k_scale(float* __restrict__ out) {
    int b = blockIdx.y;
    int idx = blockIdx.x * 256 + threadIdx.x;   // float4 index within row
    if (idx >= Cdim / 4) return;
    float inv = 1.f / g_rowsum[b];
    float4* p = (float4*)(out + (size_t)b * Cdim);
    float4 v = p[idx];
    v.x *= inv; v.y *= inv; v.z *= inv; v.w *= inv;
    p[idx] = v;
}

// ---------------- launch ----------------
extern "C" void kernel_launch(void* const* d_in, const int* in_sizes, int n_in,
                              void* d_out, int out_size) {
    const float* embds = (const float*)d_in[0];   // [256,128]
    const float* w     = (const float*)d_in[1];   // [128,8000]
    const int* labels  = (const int*)d_in[2];     // [256]
    float* out = (float*)d_out;                   // logits[256*8000] then penalties[256*8000]

    static const int kMainSmem = (KH * CT + 2 * KH * BT) * (int)sizeof(float); // 64KB
    cudaFuncSetAttribute(k_main, cudaFuncAttributeMaxDynamicSharedMemorySize, kMainSmem);

    k_norm_w<<<(CPAD + 255) / 256, 256>>>(w);
    k_prep<<<Bdim, Ddim>>>(embds, labels);

    dim3 g3(CPAD / CT, Bdim / BT);  // (63, 4)
    k_main<<<g3, 256, kMainSmem>>>(out, labels);

    dim3 g4((Cdim / 4 + 255) / 256, Bdim);  // (8, 256)
    k_scale<<<g4, 256>>>(out);
}